// round 1
// baseline (speedup 1.0000x reference)
#include <cuda_runtime.h>

#define QF 64
#define PTS_PER_WARP 512

// Zero the output (harness poisons it with 0xAA).
__global__ void perslay_zero_kernel(float* __restrict__ out, int n) {
    int i = blockIdx.x * blockDim.x + threadIdx.x;
    if (i < n) out[i] = 0.0f;
}

__device__ __forceinline__ float ex2_approx(float x) {
    float r;
    asm("ex2.approx.f32 %0, %1;" : "=f"(r) : "f"(x));
    return r;
}

// One warp processes a contiguous run of PTS_PER_WARP points and covers all
// Q=64 output features (lane l owns q=2l and q=2l+1). point_index is sorted,
// so each warp touches only ~2 segments -> accumulate in registers, flush
// with atomicAdd only at segment boundaries.
//
// exp(-(zx^2+zy^2)) is computed as ex2(-(zx'^2+zy'^2)) with the inverse
// sigmas pre-scaled by sqrt(log2 e); the negation is folded into FFMA
// operand-negation modifiers (free in SASS).
__global__ __launch_bounds__(128, 8) void perslay_kernel(
    const float2* __restrict__ xy,   // [N] (x,y)
    const int*    __restrict__ seg,  // [N] sorted segment ids
    const float*  __restrict__ sp,   // [2,QF] sample points
    const float*  __restrict__ isg,  // [2,QF] inverse sigmas
    float*        __restrict__ out,  // [D,QF]
    int n)
{
    const int warp_id = blockIdx.x * (blockDim.x >> 5) + (threadIdx.x >> 5);
    const int lane    = threadIdx.x & 31;
    const int start   = warp_id * PTS_PER_WARP;
    if (start >= n) return;
    const int end = min(start + PTS_PER_WARP, n);

    const int q0 = 2 * lane;
    const int q1 = q0 + 1;

    // sqrt(log2(e)): folds the base-2 conversion into the sigma scale.
    const float SL  = 1.2011224087864498f;
    const float ax0 = isg[q0]      * SL;
    const float ay0 = isg[QF + q0] * SL;
    const float ax1 = isg[q1]      * SL;
    const float ay1 = isg[QF + q1] * SL;
    const float bx0 = -sp[q0]      * ax0;
    const float by0 = -sp[QF + q0] * ay0;
    const float bx1 = -sp[q1]      * ax1;
    const float by1 = -sp[QF + q1] * ay1;

    float acc0 = 0.0f, acc1 = 0.0f;
    int cur = seg[start];

    #pragma unroll 4
    for (int p = start; p < end; ++p) {
        const float2 c = xy[p];     // warp-uniform address -> 1 L1 transaction
        const int    s = seg[p];    // warp-uniform
        if (s != cur) {             // uniform branch; rare (~1 per 488 points)
            atomicAdd(&out[cur * QF + q0], acc0);
            atomicAdd(&out[cur * QF + q1], acc1);
            acc0 = 0.0f;
            acc1 = 0.0f;
            cur = s;
        }
        const float zx0 = fmaf(c.x, ax0, bx0);
        const float zy0 = fmaf(c.y, ay0, by0);
        const float zx1 = fmaf(c.x, ax1, bx1);
        const float zy1 = fmaf(c.y, ay1, by1);
        const float t0  = fmaf(zx0, -zx0, -zy0 * zy0);  // = -(zx0^2 + zy0^2)
        const float t1  = fmaf(zx1, -zx1, -zy1 * zy1);
        acc0 += ex2_approx(t0);
        acc1 += ex2_approx(t1);
    }
    atomicAdd(&out[cur * QF + q0], acc0);
    atomicAdd(&out[cur * QF + q1], acc1);
}

extern "C" void kernel_launch(void* const* d_in, const int* in_sizes, int n_in,
                              void* d_out, int out_size) {
    const float2* xy  = (const float2*)d_in[0];
    const int*    seg = (const int*)   d_in[1];
    const float*  sp  = (const float*) d_in[2];
    const float*  isg = (const float*) d_in[3];
    float*        out = (float*)d_out;

    const int n = in_sizes[0] / 2;   // input is [N,2] float32

    perslay_zero_kernel<<<(out_size + 255) / 256, 256>>>(out, out_size);

    const int num_warps = (n + PTS_PER_WARP - 1) / PTS_PER_WARP;
    const int blocks    = (num_warps + 3) / 4;   // 4 warps / block
    perslay_kernel<<<blocks, 128>>>(xy, seg, sp, isg, out, n);
}

// round 2
// speedup vs baseline: 1.2789x; 1.2789x over previous
#include <cuda_runtime.h>

#define QF 64
#define PTS_PER_WARP 288   // multiple of 4; ~6.9K warps -> ~48 warps/SM

typedef unsigned long long ull;

__global__ void perslay_zero_kernel(float4* __restrict__ out, int n4) {
    int i = blockIdx.x * blockDim.x + threadIdx.x;
    if (i < n4) out[i] = make_float4(0.f, 0.f, 0.f, 0.f);
}

__device__ __forceinline__ float ex2_approx(float x) {
    float r;
    asm("ex2.approx.f32 %0, %1;" : "=f"(r) : "f"(x));
    return r;
}
__device__ __forceinline__ ull pack2(float lo, float hi) {
    ull r;
    asm("mov.b64 %0, {%1, %2};" : "=l"(r) : "f"(lo), "f"(hi));
    return r;
}
__device__ __forceinline__ void unpack2(ull v, float& lo, float& hi) {
    asm("mov.b64 {%0, %1}, %2;" : "=f"(lo), "=f"(hi) : "l"(v));
}
__device__ __forceinline__ ull fma2(ull a, ull b, ull c) {
    ull d;
    asm("fma.rn.f32x2 %0, %1, %2, %3;" : "=l"(d) : "l"(a), "l"(b), "l"(c));
    return d;
}

// t = A*x^2 + B*x + Ay*y^2 + By*y + C  (== -(ax(x-px))^2 - (ay(y-py))^2, in log2 units)
// for the lane's two q's simultaneously via f32x2, then 2x ex2 + 2x accumulate.
__device__ __forceinline__ void gmath(float x, float y,
                                      ull A, ull B, ull Ay, ull By, ull C,
                                      float& acc0, float& acc1)
{
    const ull xp = pack2(x, x);
    const ull yp = pack2(y, y);
    const ull u  = fma2(xp, A, B);
    const ull v  = fma2(xp, u, C);
    const ull w  = fma2(yp, Ay, By);
    const ull t  = fma2(yp, w, v);
    float t0, t1;
    unpack2(t, t0, t1);
    acc0 += ex2_approx(t0);
    acc1 += ex2_approx(t1);
}

__device__ __forceinline__ void flush(float* __restrict__ out, int cur, int q0,
                                      float& a0, float& a1)
{
    atomicAdd(&out[cur * QF + q0],     a0);
    atomicAdd(&out[cur * QF + q0 + 1], a1);
    a0 = 0.f;
    a1 = 0.f;
}

// One warp handles a contiguous run of points and all Q=64 features
// (lane l owns q=2l, 2l+1). Sorted point_index -> register accumulation,
// atomic flush only at segment boundaries (~1 per 488 points).
__global__ __launch_bounds__(128) void perslay_kernel(
    const float2* __restrict__ xy,
    const int*    __restrict__ seg,
    const float*  __restrict__ sp,
    const float*  __restrict__ isg,
    float*        __restrict__ out,
    int n)
{
    const int warp_id = blockIdx.x * (blockDim.x >> 5) + (threadIdx.x >> 5);
    const int lane    = threadIdx.x & 31;
    const int start   = warp_id * PTS_PER_WARP;
    if (start >= n) return;
    const int end = min(start + PTS_PER_WARP, n);

    const int q0 = 2 * lane;
    const int q1 = q0 + 1;

    // sqrt(log2 e) folded into the sigma scale so a bare ex2 replaces exp.
    const float SL = 1.2011224087864498f;
    const float px0 = sp[q0],      px1 = sp[q1];
    const float py0 = sp[QF + q0], py1 = sp[QF + q1];
    const float ax0 = isg[q0]      * SL, ax1 = isg[q1]      * SL;
    const float ay0 = isg[QF + q0] * SL, ay1 = isg[QF + q1] * SL;

    const float A0  = -ax0 * ax0,        A1  = -ax1 * ax1;
    const float Ay0 = -ay0 * ay0,        Ay1 = -ay1 * ay1;
    const float B0  = -2.f * A0  * px0,  B1  = -2.f * A1  * px1;
    const float By0 = -2.f * Ay0 * py0,  By1 = -2.f * Ay1 * py1;
    const float C0  = A0 * px0 * px0 + Ay0 * py0 * py0;
    const float C1  = A1 * px1 * px1 + Ay1 * py1 * py1;

    const ull A  = pack2(A0,  A1);
    const ull B  = pack2(B0,  B1);
    const ull Ay = pack2(Ay0, Ay1);
    const ull By = pack2(By0, By1);
    const ull C  = pack2(C0,  C1);

    const float4* __restrict__ xy4 = (const float4*)xy;  // 2 points per float4

    float acc0 = 0.f, acc1 = 0.f;
    int cur = seg[start];

    int p = start;
    for (; p + 4 <= end; p += 4) {
        const float4 c01 = xy4[p >> 1];
        const float4 c23 = xy4[(p >> 1) + 1];
        const int4   s   = *reinterpret_cast<const int4*>(seg + p);
        if (s.w == cur) {
            // sorted & s.w == cur  =>  s.x..s.w all == cur: branch-free chunk
            gmath(c01.x, c01.y, A, B, Ay, By, C, acc0, acc1);
            gmath(c01.z, c01.w, A, B, Ay, By, C, acc0, acc1);
            gmath(c23.x, c23.y, A, B, Ay, By, C, acc0, acc1);
            gmath(c23.z, c23.w, A, B, Ay, By, C, acc0, acc1);
        } else {
            if (s.x != cur) { flush(out, cur, q0, acc0, acc1); cur = s.x; }
            gmath(c01.x, c01.y, A, B, Ay, By, C, acc0, acc1);
            if (s.y != cur) { flush(out, cur, q0, acc0, acc1); cur = s.y; }
            gmath(c01.z, c01.w, A, B, Ay, By, C, acc0, acc1);
            if (s.z != cur) { flush(out, cur, q0, acc0, acc1); cur = s.z; }
            gmath(c23.x, c23.y, A, B, Ay, By, C, acc0, acc1);
            if (s.w != cur) { flush(out, cur, q0, acc0, acc1); cur = s.w; }
            gmath(c23.z, c23.w, A, B, Ay, By, C, acc0, acc1);
        }
    }
    for (; p < end; ++p) {  // tail (< 4 points)
        const float2 c = xy[p];
        const int    s = seg[p];
        if (s != cur) { flush(out, cur, q0, acc0, acc1); cur = s; }
        gmath(c.x, c.y, A, B, Ay, By, C, acc0, acc1);
    }
    flush(out, cur, q0, acc0, acc1);
}

extern "C" void kernel_launch(void* const* d_in, const int* in_sizes, int n_in,
                              void* d_out, int out_size) {
    const float2* xy  = (const float2*)d_in[0];
    const int*    seg = (const int*)   d_in[1];
    const float*  sp  = (const float*) d_in[2];
    const float*  isg = (const float*) d_in[3];
    float*        out = (float*)d_out;

    const int n = in_sizes[0] / 2;   // input is [N,2] float32

    const int n4 = out_size >> 2;    // out_size = 4096*64, divisible by 4
    perslay_zero_kernel<<<(n4 + 255) / 256, 256>>>((float4*)out, n4);

    const int num_warps = (n + PTS_PER_WARP - 1) / PTS_PER_WARP;
    const int blocks    = (num_warps + 3) / 4;   // 4 warps / block
    perslay_kernel<<<blocks, 128>>>(xy, seg, sp, isg, out, n);
}